// round 10
// baseline (speedup 1.0000x reference)
#include <cuda_runtime.h>
#include <cuda_bf16.h>
#include <stdint.h>

#define NE 8
#define DD 1024
#define RR 64
#define TT 128
#define MAXN 16384
#define S1 104          // fc1 smem stride in bf16 (96 data + 8 pad)
#define S2 200          // fc2 smem stride in bf16 (192 data + 8 pad)
#define B1SZ 39936      // fc1 buffer size
#define B2SZ 51200      // fc2 buffer size
#define HS_OFF 153600   // Hs offset (after 3x51200)
#define SMEM_TOTAL 204800

// ------------------------- device scratch ----------------------------------
__device__ int   g_counts[NE];
__device__ int   g_tok[NE * MAXN];          // encoded tok*2 + k
__device__ float g_gate[NE * MAXN];
__device__ float g_scratch[2u * MAXN * DD]; // 128 MB per-(token,k) contribution

// ------------------------- helpers -----------------------------------------
__device__ __forceinline__ uint32_t smem_u32(const void* p) {
    uint32_t a;
    asm("{ .reg .u64 t; cvta.to.shared.u64 t, %1; cvt.u32.u64 %0, t; }"
        : "=r"(a) : "l"(p));
    return a;
}
__device__ __forceinline__ void ldsm4(uint32_t* r, uint32_t addr) {
    asm volatile("ldmatrix.sync.aligned.m8n8.x4.shared.b16 {%0,%1,%2,%3}, [%4];"
                 : "=r"(r[0]), "=r"(r[1]), "=r"(r[2]), "=r"(r[3]) : "r"(addr));
}
__device__ __forceinline__ void mma16816(float* c, const uint32_t* a,
                                         const uint32_t* b) {
    asm volatile("mma.sync.aligned.m16n8k16.row.col.f32.bf16.bf16.f32 "
                 "{%0,%1,%2,%3}, {%4,%5,%6,%7}, {%8,%9}, {%0,%1,%2,%3};"
                 : "+f"(c[0]), "+f"(c[1]), "+f"(c[2]), "+f"(c[3])
                 : "r"(a[0]), "r"(a[1]), "r"(a[2]), "r"(a[3]),
                   "r"(b[0]), "r"(b[1]));
}
__device__ __forceinline__ void split2(float v, uint32_t& h, uint32_t& l) {
    __nv_bfloat16 hb = __float2bfloat16(v);
    h = (uint32_t)__bfloat16_as_ushort(hb);
    l = (uint32_t)__bfloat16_as_ushort(__float2bfloat16(v - __bfloat162float(hb)));
}
// A operand triple: per elem (h, l, h)
__device__ __forceinline__ void packA(float4 v, void* dst) {
    uint32_t h0,l0,h1,l1,h2,l2,h3,l3;
    split2(v.x,h0,l0); split2(v.y,h1,l1); split2(v.z,h2,l2); split2(v.w,h3,l3);
    uint2* d = (uint2*)dst;
    d[0] = make_uint2(h0 | (l0 << 16), h0 | (h1 << 16));
    d[1] = make_uint2(l1 | (h1 << 16), h2 | (l2 << 16));
    d[2] = make_uint2(h2 | (h3 << 16), l3 | (h3 << 16));
}
// B operand triple: per elem (h, h, l)
__device__ __forceinline__ void packB(float4 v, void* dst) {
    uint32_t h0,l0,h1,l1,h2,l2,h3,l3;
    split2(v.x,h0,l0); split2(v.y,h1,l1); split2(v.z,h2,l2); split2(v.w,h3,l3);
    uint2* d = (uint2*)dst;
    d[0] = make_uint2(h0 | (h0 << 16), l0 | (h1 << 16));
    d[1] = make_uint2(h1 | (l1 << 16), h2 | (h2 << 16));
    d[2] = make_uint2(l2 | (h3 << 16), h3 | (l3 << 16));
}

// ---------------------------------------------------------------------------
// Router: warp per 4 tokens; processes them in PAIRS so each smem Wg read is
// shared by 2 tokens (halves the crossbar traffic vs the 40us version).
// ---------------------------------------------------------------------------
__global__ void router_kernel(const float* __restrict__ x,
                              const float* __restrict__ Wg,
                              const float* __restrict__ bg, int N) {
    __shared__ float4 sWg[NE * 256];
    int t = threadIdx.x;
    const float4* Wg4 = (const float4*)Wg;
    for (int i = t; i < NE * 256; i += 256) sWg[i] = Wg4[i];
    __syncthreads();

    int warp = t >> 5, lane = t & 31;
    for (int it = 0; it < 2; it++) {
        int tokA = blockIdx.x * 32 + warp * 4 + it * 2;
        if (tokA >= N) break;
        int tokB = tokA + 1;
        bool hasB = tokB < N;
        const float4* xrA = (const float4*)(x + (size_t)tokA * DD);
        const float4* xrB = (const float4*)(x + (size_t)(hasB ? tokB : tokA) * DD);
        float acc[2][NE];
#pragma unroll
        for (int i = 0; i < 2; i++)
#pragma unroll
            for (int e = 0; e < NE; e++) acc[i][e] = 0.f;
#pragma unroll
        for (int i = 0; i < 8; i++) {
            float4 xa = xrA[i * 32 + lane];
            float4 xb = xrB[i * 32 + lane];
#pragma unroll
            for (int e = 0; e < NE; e++) {
                float4 w = sWg[e * 256 + i * 32 + lane];
                acc[0][e] = fmaf(xa.x, w.x, acc[0][e]);
                acc[0][e] = fmaf(xa.y, w.y, acc[0][e]);
                acc[0][e] = fmaf(xa.z, w.z, acc[0][e]);
                acc[0][e] = fmaf(xa.w, w.w, acc[0][e]);
                acc[1][e] = fmaf(xb.x, w.x, acc[1][e]);
                acc[1][e] = fmaf(xb.y, w.y, acc[1][e]);
                acc[1][e] = fmaf(xb.z, w.z, acc[1][e]);
                acc[1][e] = fmaf(xb.w, w.w, acc[1][e]);
            }
        }
#pragma unroll
        for (int i = 0; i < 2; i++)
#pragma unroll
            for (int e = 0; e < NE; e++) {
#pragma unroll
                for (int off = 16; off; off >>= 1)
                    acc[i][e] += __shfl_xor_sync(0xffffffffu, acc[i][e], off);
            }
        if (lane == 0) {
#pragma unroll
            for (int i = 0; i < 2; i++) {
                int tok = tokA + i;
                if (tok >= N) break;
                float l[NE];
#pragma unroll
                for (int e = 0; e < NE; e++) l[e] = acc[i][e] + bg[e];
                int i0 = 0;
#pragma unroll
                for (int e = 1; e < NE; e++) if (l[e] > l[i0]) i0 = e;
                int i1 = (i0 == 0) ? 1 : 0;
#pragma unroll
                for (int e = 0; e < NE; e++) if (e != i0 && l[e] > l[i1]) i1 = e;
                float ex = expf(l[i1] - l[i0]);
                float inv = 1.f / (1.f + ex);
                int p0 = atomicAdd(&g_counts[i0], 1);
                g_tok[i0 * MAXN + p0]  = tok * 2;
                g_gate[i0 * MAXN + p0] = inv;
                int p1 = atomicAdd(&g_counts[i1], 1);
                g_tok[i1 * MAXN + p1]  = tok * 2 + 1;
                g_gate[i1 * MAXN + p1] = ex * inv;
            }
        }
    }
}

// ---------------------------------------------------------------------------
// Expert kernel: 512 threads, TRIPLE-buffered smem with 2-chunk-ahead LDG
// pipeline (global-load latency gets ~2 chunk-times to land before its STS).
//   fc1: D1[128,64] = X3[128,3072] @ W1_3[64,3072]^T   (3 bufs x 39936)
//   epi: H3 -> smem at +153600
//   fc2: 8 chunks of 128 cols, W2 3 bufs x 51200.
// ---------------------------------------------------------------------------
__global__ void __launch_bounds__(512, 1)
expert_kernel(const float* __restrict__ x,
              const float* __restrict__ W1,
              const float* __restrict__ W2) {
    extern __shared__ char dynsm[];
    __shared__ int   s_tok[TT];
    __shared__ float s_gate[TT];

    int e = blockIdx.x, tile = blockIdx.y;
    int cnt = g_counts[e];
    int base = tile * TT;
    if (base >= cnt) return;
    int nt = min(TT, cnt - base);

    int t = threadIdx.x, wid = t >> 5, l = t & 31;
    int wm = wid & 3, wn = wid >> 2;   // warp grid 4(M) x 4(N)

    if (t < TT) {
        if (t < nt) {
            s_tok[t]  = g_tok[e * MAXN + base + t];
            s_gate[t] = g_gate[e * MAXN + base + t];
        } else {
            s_tok[t]  = g_tok[e * MAXN + base];
            s_gate[t] = 0.f;
        }
    }
    __syncthreads();

    char* bufs = dynsm;
    char* Hs   = dynsm + HS_OFF;
    const float* W1e = W1 + (size_t)e * RR * DD;
    const float* W2e = W2 + (size_t)e * DD * RR;

    uint32_t a1_lo = (uint32_t)(((l & 7) + ((l >> 3) & 1) * 8) * S1 * 2 + (l >> 4) * 16);
    uint32_t b1_lo = (uint32_t)(((l & 7) + (l >> 4) * 8) * S1 * 2 + ((l >> 3) & 1) * 16);
    uint32_t a2_lo = (uint32_t)(((l & 7) + ((l >> 3) & 1) * 8) * S2 * 2 + (l >> 4) * 16);
    uint32_t b2_lo = (uint32_t)(((l & 7) + (l >> 4) * 8) * S2 * 2 + ((l >> 3) & 1) * 16);
    uint32_t bufs_a = smem_u32(bufs);

    // ================= fc1 (warp tile 32M x 16N) =================
    float acc[2][2][4];
#pragma unroll
    for (int i = 0; i < 2; i++)
#pragma unroll
        for (int j = 0; j < 2; j++)
#pragma unroll
            for (int k = 0; k < 4; k++) acc[i][j][k] = 0.f;

    float4 pa[2][2], pb1[2];      // two register sets (2-deep pipeline)
    auto ldg1 = [&](int c, int s) {
#pragma unroll
        for (int j = 0; j < 2; j++) {
            int idx = t + j * 512;
            int r = idx >> 3, c4 = idx & 7;
            int tok = s_tok[r] >> 1;
            pa[s][j] = *(const float4*)(x + (size_t)tok * DD + c * 32 + c4 * 4);
        }
        {
            int r = t >> 3, c4 = t & 7;
            pb1[s] = *(const float4*)(W1e + (size_t)r * DD + c * 32 + c4 * 4);
        }
    };
    auto sts1 = [&](int buf, int s) {
        char* As = bufs + buf * B1SZ;
        char* Bs = As + 26624;
#pragma unroll
        for (int j = 0; j < 2; j++) {
            int idx = t + j * 512;
            int r = idx >> 3, c4 = idx & 7;
            packA(pa[s][j], As + r * S1 * 2 + c4 * 24);
        }
        {
            int r = t >> 3, c4 = t & 7;
            packB(pb1[s], Bs + r * S1 * 2 + c4 * 24);
        }
    };

    ldg1(0, 0); sts1(0, 0);
    ldg1(1, 1);
    __syncthreads();

    for (int c = 0; c < 32; c++) {
        if (c + 2 < 32) ldg1(c + 2, c & 1);        // lands ~2 chunks later
        uint32_t Aaddr = bufs_a + (c % 3) * B1SZ;
        uint32_t Baddr = Aaddr + 26624;
#pragma unroll
        for (int kk = 0; kk < 6; kk++) {
            uint32_t a[2][4], b[4];
#pragma unroll
            for (int mt = 0; mt < 2; mt++)
                ldsm4(a[mt], Aaddr + (wm * 32 + mt * 16) * S1 * 2 + kk * 32 + a1_lo);
            ldsm4(b, Baddr + (wn * 16) * S1 * 2 + kk * 32 + b1_lo);
#pragma unroll
            for (int mt = 0; mt < 2; mt++)
#pragma unroll
                for (int ntl = 0; ntl < 2; ntl++)
                    mma16816(acc[mt][ntl], a[mt], &b[ntl * 2]);
        }
        if (c + 1 < 32) sts1((c + 1) % 3, (c + 1) & 1);
        __syncthreads();
    }

    // ===== fc2 prefetch (issue before epilogue to hide latency) =====
    float4 pw[2][4];
    auto ldg2 = [&](int nch, int s) {
#pragma unroll
        for (int j = 0; j < 4; j++) {
            int idx = t + j * 512;
            int r = idx >> 4, c4 = idx & 15;
            pw[s][j] = *(const float4*)(W2e + (size_t)(nch * TT + r) * RR + c4 * 4);
        }
    };
    auto sts2 = [&](int buf, int s) {
        char* Ws = bufs + buf * B2SZ;
#pragma unroll
        for (int j = 0; j < 4; j++) {
            int idx = t + j * 512;
            int r = idx >> 4, c4 = idx & 15;
            packB(pw[s][j], Ws + r * S2 * 2 + c4 * 24);
        }
    };
    ldg2(0, 0);
    ldg2(1, 1);

    // ============ epilogue: gelu*gate*2 -> triple-split H in smem ===========
#pragma unroll
    for (int mt = 0; mt < 2; mt++) {
#pragma unroll
        for (int ntl = 0; ntl < 2; ntl++) {
#pragma unroll
            for (int half = 0; half < 2; half++) {
                int r = wm * 32 + mt * 16 + half * 8 + (l >> 2);
                float gs = s_gate[r] * 2.0f;   // SCALING = 128/64
                float v0 = acc[mt][ntl][half * 2 + 0];
                float v1 = acc[mt][ntl][half * 2 + 1];
                float g0 = 0.5f * v0 * (1.f + erff(v0 * 0.70710678118654752f)) * gs;
                float g1 = 0.5f * v1 * (1.f + erff(v1 * 0.70710678118654752f)) * gs;
                int n = wn * 16 + ntl * 8 + (l & 3) * 2;
                uint32_t h0, l0, h1, l1;
                split2(g0, h0, l0); split2(g1, h1, l1);
                uint32_t* d = (uint32_t*)(Hs + r * S2 * 2 + n * 6);
                d[0] = h0 | (l0 << 16);
                d[1] = h0 | (h1 << 16);
                d[2] = l1 | (h1 << 16);
            }
        }
    }
    sts2(0, 0);
    __syncthreads();

    // ================= fc2 (warp tile 32M x 32N) =================
    uint32_t HsA = smem_u32(Hs);
    for (int n = 0; n < 8; n++) {
        if (n + 2 < 8) ldg2(n + 2, n & 1);
        float acc2[2][4][4];
#pragma unroll
        for (int i = 0; i < 2; i++)
#pragma unroll
            for (int j = 0; j < 4; j++)
#pragma unroll
                for (int k = 0; k < 4; k++) acc2[i][j][k] = 0.f;

        uint32_t Waddr = bufs_a + (n % 3) * B2SZ;
#pragma unroll
        for (int kk = 0; kk < 12; kk++) {
            uint32_t a[2][4], b[2][4];
#pragma unroll
            for (int mt = 0; mt < 2; mt++)
                ldsm4(a[mt], HsA + (wm * 32 + mt * 16) * S2 * 2 + kk * 32 + a2_lo);
#pragma unroll
            for (int pr = 0; pr < 2; pr++)
                ldsm4(b[pr], Waddr + (wn * 32 + pr * 16) * S2 * 2 + kk * 32 + b2_lo);
#pragma unroll
            for (int mt = 0; mt < 2; mt++)
#pragma unroll
                for (int ntl = 0; ntl < 4; ntl++)
                    mma16816(acc2[mt][ntl], a[mt], &b[ntl >> 1][(ntl & 1) * 2]);
        }
        // store to scratch
#pragma unroll
        for (int mt = 0; mt < 2; mt++) {
#pragma unroll
            for (int half = 0; half < 2; half++) {
                int r = wm * 32 + mt * 16 + half * 8 + (l >> 2);
                if (r < nt) {
                    int slot = s_tok[r];
                    float* dst = g_scratch + (size_t)slot * DD + n * 128
                               + wn * 32 + (l & 3) * 2;
#pragma unroll
                    for (int ntl = 0; ntl < 4; ntl++)
                        *(float2*)(dst + ntl * 8) =
                            make_float2(acc2[mt][ntl][half * 2 + 0],
                                        acc2[mt][ntl][half * 2 + 1]);
                }
            }
        }
        if (n + 1 < 8) sts2((n + 1) % 3, (n + 1) & 1);
        __syncthreads();
    }
}

// ---------------------------------------------------------------------------
__global__ void combine_kernel(float* __restrict__ out, int N) {
    int i = blockIdx.x * blockDim.x + threadIdx.x;
    int total = N * (DD / 4);
    if (i >= total) return;
    int tok = i >> 8;
    int dd  = i & 255;
    const float4* s = (const float4*)g_scratch;
    float4 a = s[(size_t)tok * 512 + dd];
    float4 b = s[(size_t)tok * 512 + 256 + dd];
    float4 o;
    o.x = a.x + b.x; o.y = a.y + b.y; o.z = a.z + b.z; o.w = a.w + b.w;
    ((float4*)out)[i] = o;
}

// ---------------------------------------------------------------------------
extern "C" void kernel_launch(void* const* d_in, const int* in_sizes, int n_in,
                              void* d_out, int out_size) {
    const float* x  = (const float*)d_in[0];
    const float* Wg = (const float*)d_in[1];
    const float* bg = (const float*)d_in[2];
    const float* W1 = (const float*)d_in[3];
    const float* W2 = (const float*)d_in[4];
    float* out = (float*)d_out;
    int N = in_sizes[0] / DD;

    cudaFuncSetAttribute(expert_kernel,
                         cudaFuncAttributeMaxDynamicSharedMemorySize, SMEM_TOTAL);

    void* counts_ptr = nullptr;
    cudaGetSymbolAddress(&counts_ptr, g_counts);
    cudaMemsetAsync(counts_ptr, 0, NE * sizeof(int), 0);

    router_kernel<<<(N + 31) / 32, 256>>>(x, Wg, bg, N);

    dim3 egrid(NE, 128);
    expert_kernel<<<egrid, 512, SMEM_TOTAL>>>(x, W1, W2);

    int total = N * (DD / 4);
    combine_kernel<<<(total + 255) / 256, 256>>>(out, N);
}

// round 11
// speedup vs baseline: 1.4179x; 1.4179x over previous
#include <cuda_runtime.h>
#include <cuda_fp16.h>
#include <stdint.h>

#define NE 8
#define DD 1024
#define RR 64
#define TT 128
#define MAXN 16384
#define S1B 144         // fc1 smem row stride BYTES (64 fp16 data + 8 pad)
#define S2B 272         // fc2 smem row stride BYTES (128 fp16 data + 8 pad)
#define B1SZ 27648      // fc1 buffer: A 128*144 + B 64*144
#define B1_BOFF 18432   // B tile offset inside fc1 buffer
#define B2SZ 34816      // fc2 W buffer: 128*272
#define HS_OFF 69632    // Hs offset (after 2x34816)
#define SMEM_TOTAL 104448

// ------------------------- device scratch ----------------------------------
__device__ int   g_counts[NE];
__device__ int   g_tok[NE * MAXN];          // encoded tok*2 + k
__device__ float g_gate[NE * MAXN];
__device__ float g_scratch[2u * MAXN * DD]; // 128 MB per-(token,k) contribution

// ------------------------- helpers -----------------------------------------
__device__ __forceinline__ uint32_t smem_u32(const void* p) {
    uint32_t a;
    asm("{ .reg .u64 t; cvta.to.shared.u64 t, %1; cvt.u32.u64 %0, t; }"
        : "=r"(a) : "l"(p));
    return a;
}
__device__ __forceinline__ void ldsm4(uint32_t* r, uint32_t addr) {
    asm volatile("ldmatrix.sync.aligned.m8n8.x4.shared.b16 {%0,%1,%2,%3}, [%4];"
                 : "=r"(r[0]), "=r"(r[1]), "=r"(r[2]), "=r"(r[3]) : "r"(addr));
}
__device__ __forceinline__ void mma16816(float* c, const uint32_t* a,
                                         const uint32_t* b) {
    asm volatile("mma.sync.aligned.m16n8k16.row.col.f32.f16.f16.f32 "
                 "{%0,%1,%2,%3}, {%4,%5,%6,%7}, {%8,%9}, {%0,%1,%2,%3};"
                 : "+f"(c[0]), "+f"(c[1]), "+f"(c[2]), "+f"(c[3])
                 : "r"(a[0]), "r"(a[1]), "r"(a[2]), "r"(a[3]),
                   "r"(b[0]), "r"(b[1]));
}
// fp16 2-term split. A elem -> (h, l) packed in one u32 (K-consecutive).
__device__ __forceinline__ uint32_t packA1(float v) {
    __half h = __float2half_rn(v);
    __half l = __float2half_rn(v - __half2float(h));
    return (uint32_t)__half_as_ushort(h) | ((uint32_t)__half_as_ushort(l) << 16);
}
// B elem -> (h, h) packed in one u32.
__device__ __forceinline__ uint32_t packB1(float v) {
    uint32_t u = (uint32_t)__half_as_ushort(__float2half_rn(v));
    return u | (u << 16);
}
__device__ __forceinline__ uint4 packA4(float4 v) {
    return make_uint4(packA1(v.x), packA1(v.y), packA1(v.z), packA1(v.w));
}
__device__ __forceinline__ uint4 packB4(float4 v) {
    return make_uint4(packB1(v.x), packB1(v.y), packB1(v.z), packB1(v.w));
}

// ---------------------------------------------------------------------------
// Router (verified 38.5us): warp per 4 tokens, pairs share each Wg smem read.
// ---------------------------------------------------------------------------
__global__ void router_kernel(const float* __restrict__ x,
                              const float* __restrict__ Wg,
                              const float* __restrict__ bg, int N) {
    __shared__ float4 sWg[NE * 256];
    int t = threadIdx.x;
    const float4* Wg4 = (const float4*)Wg;
    for (int i = t; i < NE * 256; i += 256) sWg[i] = Wg4[i];
    __syncthreads();

    int warp = t >> 5, lane = t & 31;
    for (int it = 0; it < 2; it++) {
        int tokA = blockIdx.x * 32 + warp * 4 + it * 2;
        if (tokA >= N) break;
        int tokB = tokA + 1;
        bool hasB = tokB < N;
        const float4* xrA = (const float4*)(x + (size_t)tokA * DD);
        const float4* xrB = (const float4*)(x + (size_t)(hasB ? tokB : tokA) * DD);
        float acc[2][NE];
#pragma unroll
        for (int i = 0; i < 2; i++)
#pragma unroll
            for (int e = 0; e < NE; e++) acc[i][e] = 0.f;
#pragma unroll
        for (int i = 0; i < 8; i++) {
            float4 xa = xrA[i * 32 + lane];
            float4 xb = xrB[i * 32 + lane];
#pragma unroll
            for (int e = 0; e < NE; e++) {
                float4 w = sWg[e * 256 + i * 32 + lane];
                acc[0][e] = fmaf(xa.x, w.x, acc[0][e]);
                acc[0][e] = fmaf(xa.y, w.y, acc[0][e]);
                acc[0][e] = fmaf(xa.z, w.z, acc[0][e]);
                acc[0][e] = fmaf(xa.w, w.w, acc[0][e]);
                acc[1][e] = fmaf(xb.x, w.x, acc[1][e]);
                acc[1][e] = fmaf(xb.y, w.y, acc[1][e]);
                acc[1][e] = fmaf(xb.z, w.z, acc[1][e]);
                acc[1][e] = fmaf(xb.w, w.w, acc[1][e]);
            }
        }
#pragma unroll
        for (int i = 0; i < 2; i++)
#pragma unroll
            for (int e = 0; e < NE; e++) {
#pragma unroll
                for (int off = 16; off; off >>= 1)
                    acc[i][e] += __shfl_xor_sync(0xffffffffu, acc[i][e], off);
            }
        if (lane == 0) {
#pragma unroll
            for (int i = 0; i < 2; i++) {
                int tok = tokA + i;
                if (tok >= N) break;
                float l[NE];
#pragma unroll
                for (int e = 0; e < NE; e++) l[e] = acc[i][e] + bg[e];
                int i0 = 0;
#pragma unroll
                for (int e = 1; e < NE; e++) if (l[e] > l[i0]) i0 = e;
                int i1 = (i0 == 0) ? 1 : 0;
#pragma unroll
                for (int e = 0; e < NE; e++) if (e != i0 && l[e] > l[i1]) i1 = e;
                float ex = expf(l[i1] - l[i0]);
                float inv = 1.f / (1.f + ex);
                int p0 = atomicAdd(&g_counts[i0], 1);
                g_tok[i0 * MAXN + p0]  = tok * 2;
                g_gate[i0 * MAXN + p0] = inv;
                int p1 = atomicAdd(&g_counts[i1], 1);
                g_tok[i1 * MAXN + p1]  = tok * 2 + 1;
                g_gate[i1 * MAXN + p1] = ex * inv;
            }
        }
    }
}

// ---------------------------------------------------------------------------
// Expert kernel: fp16 2-term split (K x2, 33% fewer MMAs than bf16 triple).
//   fc1: D1[128,64] = X2[128,2048] @ W1_2[64,2048]^T   (dbl-buf 2x27648)
//   epi: H2 = split(gelu(D1)*gate*2) -> smem at +69632
//   fc2: 8 chunks of 128 cols: D2 = H2[128,128] @ W2_2[128,128]^T
// Warp grid 4M x 2N (8 warps, 256 threads) -- R3-verified structure.
// ---------------------------------------------------------------------------
__global__ void __launch_bounds__(256, 1)
expert_kernel(const float* __restrict__ x,
              const float* __restrict__ W1,
              const float* __restrict__ W2) {
    extern __shared__ char dynsm[];
    __shared__ int   s_tok[TT];
    __shared__ float s_gate[TT];

    int e = blockIdx.x, tile = blockIdx.y;
    int cnt = g_counts[e];
    int base = tile * TT;
    if (base >= cnt) return;
    int nt = min(TT, cnt - base);

    int t = threadIdx.x, wid = t >> 5, l = t & 31;
    int wm = wid & 3, wn = wid >> 2;   // warp grid 4(M) x 2(N)

    if (t < TT) {
        if (t < nt) {
            s_tok[t]  = g_tok[e * MAXN + base + t];
            s_gate[t] = g_gate[e * MAXN + base + t];
        } else {
            s_tok[t]  = g_tok[e * MAXN + base];
            s_gate[t] = 0.f;
        }
    }
    __syncthreads();

    char* bufs = dynsm;
    char* Hs   = dynsm + HS_OFF;
    const float* W1e = W1 + (size_t)e * RR * DD;
    const float* W2e = W2 + (size_t)e * DD * RR;

    uint32_t a1_lo = (uint32_t)(((l & 7) + ((l >> 3) & 1) * 8) * S1B + (l >> 4) * 16);
    uint32_t b1_lo = (uint32_t)(((l & 7) + (l >> 4) * 8) * S1B + ((l >> 3) & 1) * 16);
    uint32_t a2_lo = (uint32_t)(((l & 7) + ((l >> 3) & 1) * 8) * S2B + (l >> 4) * 16);
    uint32_t b2_lo = (uint32_t)(((l & 7) + (l >> 4) * 8) * S2B + ((l >> 3) & 1) * 16);
    uint32_t bufs_a = smem_u32(bufs);

    // ================= fc1 (warp tile 32M x 32N) =================
    float acc[2][4][4];
#pragma unroll
    for (int i = 0; i < 2; i++)
#pragma unroll
        for (int j = 0; j < 4; j++)
#pragma unroll
            for (int k = 0; k < 4; k++) acc[i][j][k] = 0.f;

    float4 pa[4], pb[2];
    auto ldg1 = [&](int c) {
#pragma unroll
        for (int j = 0; j < 4; j++) {
            int idx = t + j * 256;
            int r = idx >> 3, c4 = idx & 7;
            int tok = s_tok[r] >> 1;
            pa[j] = *(const float4*)(x + (size_t)tok * DD + c * 32 + c4 * 4);
        }
#pragma unroll
        for (int j = 0; j < 2; j++) {
            int idx = t + j * 256;
            int r = idx >> 3, c4 = idx & 7;
            pb[j] = *(const float4*)(W1e + (size_t)r * DD + c * 32 + c4 * 4);
        }
    };
    auto sts1 = [&](int buf) {
        char* As = bufs + buf * B1SZ;
        char* Bs = As + B1_BOFF;
#pragma unroll
        for (int j = 0; j < 4; j++) {
            int idx = t + j * 256;
            int r = idx >> 3, c4 = idx & 7;
            *(uint4*)(As + r * S1B + c4 * 16) = packA4(pa[j]);
        }
#pragma unroll
        for (int j = 0; j < 2; j++) {
            int idx = t + j * 256;
            int r = idx >> 3, c4 = idx & 7;
            *(uint4*)(Bs + r * S1B + c4 * 16) = packB4(pb[j]);
        }
    };

    ldg1(0); sts1(0);
    __syncthreads();

    for (int c = 0; c < 32; c++) {
        int buf = c & 1;
        if (c + 1 < 32) ldg1(c + 1);
        uint32_t Aaddr = bufs_a + buf * B1SZ;
        uint32_t Baddr = Aaddr + B1_BOFF;
#pragma unroll
        for (int kk = 0; kk < 4; kk++) {
            uint32_t a[2][4], b[2][4];
#pragma unroll
            for (int mt = 0; mt < 2; mt++)
                ldsm4(a[mt], Aaddr + (wm * 32 + mt * 16) * S1B + kk * 32 + a1_lo);
#pragma unroll
            for (int pr = 0; pr < 2; pr++)
                ldsm4(b[pr], Baddr + (wn * 32 + pr * 16) * S1B + kk * 32 + b1_lo);
#pragma unroll
            for (int mt = 0; mt < 2; mt++)
#pragma unroll
                for (int ntl = 0; ntl < 4; ntl++)
                    mma16816(acc[mt][ntl], a[mt], &b[ntl >> 1][(ntl & 1) * 2]);
        }
        if (c + 1 < 32) sts1((c + 1) & 1);
        __syncthreads();
    }

    // ============ epilogue: gelu*gate*2 -> fp16 (h,l) H in smem ============
#pragma unroll
    for (int mt = 0; mt < 2; mt++) {
#pragma unroll
        for (int ntl = 0; ntl < 4; ntl++) {
#pragma unroll
            for (int half = 0; half < 2; half++) {
                int r = wm * 32 + mt * 16 + half * 8 + (l >> 2);
                float gs = s_gate[r] * 2.0f;   // SCALING = 128/64
                float v0 = acc[mt][ntl][half * 2 + 0];
                float v1 = acc[mt][ntl][half * 2 + 1];
                float g0 = 0.5f * v0 * (1.f + erff(v0 * 0.70710678118654752f)) * gs;
                float g1 = 0.5f * v1 * (1.f + erff(v1 * 0.70710678118654752f)) * gs;
                int n = wn * 32 + ntl * 8 + (l & 3) * 2;
                *(uint2*)(Hs + r * S2B + n * 4) =
                    make_uint2(packA1(g0), packA1(g1));
            }
        }
    }
    __syncthreads();

    // ================= fc2 (warp tile 32M x 64N) =================
    uint32_t HsA = smem_u32(Hs);
    float4 pw[8];
    auto ldg2 = [&](int nch) {
#pragma unroll
        for (int j = 0; j < 8; j++) {
            int idx = t + j * 256;
            int r = idx >> 4, c4 = idx & 15;
            pw[j] = *(const float4*)(W2e + (size_t)(nch * TT + r) * RR + c4 * 4);
        }
    };
    auto sts2 = [&](int buf) {
        char* Ws = bufs + buf * B2SZ;
#pragma unroll
        for (int j = 0; j < 8; j++) {
            int idx = t + j * 256;
            int r = idx >> 4, c4 = idx & 15;
            *(uint4*)(Ws + r * S2B + c4 * 16) = packB4(pw[j]);
        }
    };

    ldg2(0); sts2(0);
    __syncthreads();

    for (int n = 0; n < 8; n++) {
        int buf = n & 1;
        if (n + 1 < 8) ldg2(n + 1);
        float acc2[2][8][4];
#pragma unroll
        for (int i = 0; i < 2; i++)
#pragma unroll
            for (int j = 0; j < 8; j++)
#pragma unroll
                for (int k = 0; k < 4; k++) acc2[i][j][k] = 0.f;

        uint32_t Waddr = bufs_a + buf * B2SZ;
#pragma unroll
        for (int kk = 0; kk < 8; kk++) {
            uint32_t a[2][4], b[4][4];
#pragma unroll
            for (int mt = 0; mt < 2; mt++)
                ldsm4(a[mt], HsA + (wm * 32 + mt * 16) * S2B + kk * 32 + a2_lo);
#pragma unroll
            for (int pr = 0; pr < 4; pr++)
                ldsm4(b[pr], Waddr + (wn * 64 + pr * 16) * S2B + kk * 32 + b2_lo);
#pragma unroll
            for (int mt = 0; mt < 2; mt++)
#pragma unroll
                for (int ntl = 0; ntl < 8; ntl++)
                    mma16816(acc2[mt][ntl], a[mt], &b[ntl >> 1][(ntl & 1) * 2]);
        }
        // store to scratch
#pragma unroll
        for (int mt = 0; mt < 2; mt++) {
#pragma unroll
            for (int half = 0; half < 2; half++) {
                int r = wm * 32 + mt * 16 + half * 8 + (l >> 2);
                if (r < nt) {
                    int slot = s_tok[r];
                    float* dst = g_scratch + (size_t)slot * DD + n * 128
                               + wn * 64 + (l & 3) * 2;
#pragma unroll
                    for (int ntl = 0; ntl < 8; ntl++)
                        *(float2*)(dst + ntl * 8) =
                            make_float2(acc2[mt][ntl][half * 2 + 0],
                                        acc2[mt][ntl][half * 2 + 1]);
                }
            }
        }
        if (n + 1 < 8) sts2((n + 1) & 1);
        __syncthreads();
    }
}

// ---------------------------------------------------------------------------
__global__ void combine_kernel(float* __restrict__ out, int N) {
    int i = blockIdx.x * blockDim.x + threadIdx.x;
    int total = N * (DD / 4);
    if (i >= total) return;
    int tok = i >> 8;
    int dd  = i & 255;
    const float4* s = (const float4*)g_scratch;
    float4 a = s[(size_t)tok * 512 + dd];
    float4 b = s[(size_t)tok * 512 + 256 + dd];
    float4 o;
    o.x = a.x + b.x; o.y = a.y + b.y; o.z = a.z + b.z; o.w = a.w + b.w;
    ((float4*)out)[i] = o;
}

// ---------------------------------------------------------------------------
extern "C" void kernel_launch(void* const* d_in, const int* in_sizes, int n_in,
                              void* d_out, int out_size) {
    const float* x  = (const float*)d_in[0];
    const float* Wg = (const float*)d_in[1];
    const float* bg = (const float*)d_in[2];
    const float* W1 = (const float*)d_in[3];
    const float* W2 = (const float*)d_in[4];
    float* out = (float*)d_out;
    int N = in_sizes[0] / DD;

    cudaFuncSetAttribute(expert_kernel,
                         cudaFuncAttributeMaxDynamicSharedMemorySize, SMEM_TOTAL);

    void* counts_ptr = nullptr;
    cudaGetSymbolAddress(&counts_ptr, g_counts);
    cudaMemsetAsync(counts_ptr, 0, NE * sizeof(int), 0);

    router_kernel<<<(N + 31) / 32, 256>>>(x, Wg, bg, N);

    dim3 egrid(NE, 128);
    expert_kernel<<<egrid, 256, SMEM_TOTAL>>>(x, W1, W2);

    int total = N * (DD / 4);
    combine_kernel<<<(total + 255) / 256, 256>>>(out, N);
}

// round 12
// speedup vs baseline: 1.8561x; 1.3090x over previous
#include <cuda_runtime.h>
#include <cuda_fp16.h>
#include <stdint.h>

#define NE 8
#define DD 1024
#define RR 64
#define TT 128
#define MAXN 16384
#define S1B 144         // fc1 smem row stride BYTES (64 fp16 = 128B data + 16 pad)
#define S2B 144         // fc2 smem row stride BYTES (64 fp16 = 128B data + 16 pad)
#define B1SZ 27648      // fc1 buffer: A 128*144 + B 64*144
#define B1_BOFF 18432   // B tile offset inside fc1 buffer
#define B2SZ 18432      // fc2 W buffer: 128*144
#define HS_OFF 55296    // Hs offset (after 2x27648 fc1 bufs; fc2 bufs reuse [0,36864))
#define SMEM_TOTAL 73728

// ------------------------- device scratch ----------------------------------
__device__ int   g_counts[NE];
__device__ int   g_tok[NE * MAXN];          // encoded tok*2 + k
__device__ float g_gate[NE * MAXN];
__device__ float g_scratch[2u * MAXN * DD]; // 128 MB per-(token,k) contribution

// ------------------------- helpers -----------------------------------------
__device__ __forceinline__ uint32_t smem_u32(const void* p) {
    uint32_t a;
    asm("{ .reg .u64 t; cvta.to.shared.u64 t, %1; cvt.u32.u64 %0, t; }"
        : "=r"(a) : "l"(p));
    return a;
}
__device__ __forceinline__ void ldsm4(uint32_t* r, uint32_t addr) {
    asm volatile("ldmatrix.sync.aligned.m8n8.x4.shared.b16 {%0,%1,%2,%3}, [%4];"
                 : "=r"(r[0]), "=r"(r[1]), "=r"(r[2]), "=r"(r[3]) : "r"(addr));
}
__device__ __forceinline__ void mma16816(float* c, const uint32_t* a,
                                         const uint32_t* b) {
    asm volatile("mma.sync.aligned.m16n8k16.row.col.f32.f16.f16.f32 "
                 "{%0,%1,%2,%3}, {%4,%5,%6,%7}, {%8,%9}, {%0,%1,%2,%3};"
                 : "+f"(c[0]), "+f"(c[1]), "+f"(c[2]), "+f"(c[3])
                 : "r"(a[0]), "r"(a[1]), "r"(a[2]), "r"(a[3]),
                   "r"(b[0]), "r"(b[1]));
}
__device__ __forceinline__ uint32_t h2(float a, float b) {
    __half2 v = __floats2half2_rn(a, b);
    return *(uint32_t*)&v;
}
// 8 consecutive fp32 -> 8 fp16 packed in uint4
__device__ __forceinline__ uint4 pack8(float4 a, float4 b) {
    return make_uint4(h2(a.x, a.y), h2(a.z, a.w), h2(b.x, b.y), h2(b.z, b.w));
}

// ---------------------------------------------------------------------------
// Router (verified ~39us): warp per 4 tokens, pairs share each Wg smem read.
// ---------------------------------------------------------------------------
__global__ void router_kernel(const float* __restrict__ x,
                              const float* __restrict__ Wg,
                              const float* __restrict__ bg, int N) {
    __shared__ float4 sWg[NE * 256];
    int t = threadIdx.x;
    const float4* Wg4 = (const float4*)Wg;
    for (int i = t; i < NE * 256; i += 256) sWg[i] = Wg4[i];
    __syncthreads();

    int warp = t >> 5, lane = t & 31;
    for (int it = 0; it < 2; it++) {
        int tokA = blockIdx.x * 32 + warp * 4 + it * 2;
        if (tokA >= N) break;
        int tokB = tokA + 1;
        bool hasB = tokB < N;
        const float4* xrA = (const float4*)(x + (size_t)tokA * DD);
        const float4* xrB = (const float4*)(x + (size_t)(hasB ? tokB : tokA) * DD);
        float acc[2][NE];
#pragma unroll
        for (int i = 0; i < 2; i++)
#pragma unroll
            for (int e = 0; e < NE; e++) acc[i][e] = 0.f;
#pragma unroll
        for (int i = 0; i < 8; i++) {
            float4 xa = xrA[i * 32 + lane];
            float4 xb = xrB[i * 32 + lane];
#pragma unroll
            for (int e = 0; e < NE; e++) {
                float4 w = sWg[e * 256 + i * 32 + lane];
                acc[0][e] = fmaf(xa.x, w.x, acc[0][e]);
                acc[0][e] = fmaf(xa.y, w.y, acc[0][e]);
                acc[0][e] = fmaf(xa.z, w.z, acc[0][e]);
                acc[0][e] = fmaf(xa.w, w.w, acc[0][e]);
                acc[1][e] = fmaf(xb.x, w.x, acc[1][e]);
                acc[1][e] = fmaf(xb.y, w.y, acc[1][e]);
                acc[1][e] = fmaf(xb.z, w.z, acc[1][e]);
                acc[1][e] = fmaf(xb.w, w.w, acc[1][e]);
            }
        }
#pragma unroll
        for (int i = 0; i < 2; i++)
#pragma unroll
            for (int e = 0; e < NE; e++) {
#pragma unroll
                for (int off = 16; off; off >>= 1)
                    acc[i][e] += __shfl_xor_sync(0xffffffffu, acc[i][e], off);
            }
        if (lane == 0) {
#pragma unroll
            for (int i = 0; i < 2; i++) {
                int tok = tokA + i;
                if (tok >= N) break;
                float l[NE];
#pragma unroll
                for (int e = 0; e < NE; e++) l[e] = acc[i][e] + bg[e];
                int i0 = 0;
#pragma unroll
                for (int e = 1; e < NE; e++) if (l[e] > l[i0]) i0 = e;
                int i1 = (i0 == 0) ? 1 : 0;
#pragma unroll
                for (int e = 0; e < NE; e++) if (e != i0 && l[e] > l[i1]) i1 = e;
                float ex = expf(l[i1] - l[i0]);
                float inv = 1.f / (1.f + ex);
                int p0 = atomicAdd(&g_counts[i0], 1);
                g_tok[i0 * MAXN + p0]  = tok * 2;
                g_gate[i0 * MAXN + p0] = inv;
                int p1 = atomicAdd(&g_counts[i1], 1);
                g_tok[i1 * MAXN + p1]  = tok * 2 + 1;
                g_gate[i1 * MAXN + p1] = ex * inv;
            }
        }
    }
}

// ---------------------------------------------------------------------------
// Expert kernel: PURE fp16 (no split) -> 8192 MMAs/block (3x fewer than bf16
// triple, 2x fewer than fp16 split).
//   fc1: D1[128,64] = Xh[128,1024] @ W1h[64,1024]^T   (16 chunks of 64k, dbl-buf)
//   epi: Hh = fp16(gelu(D1)*gate*2) -> smem at +55296
//   fc2: 8 chunks of 128 cols: D2 = Hh[128,64] @ W2h[128,64]^T
// Warp grid 4M x 2N (8 warps, 256 threads).
// ---------------------------------------------------------------------------
__global__ void __launch_bounds__(256, 1)
expert_kernel(const float* __restrict__ x,
              const float* __restrict__ W1,
              const float* __restrict__ W2) {
    extern __shared__ char dynsm[];
    __shared__ int   s_tok[TT];
    __shared__ float s_gate[TT];

    int e = blockIdx.x, tile = blockIdx.y;
    int cnt = g_counts[e];
    int base = tile * TT;
    if (base >= cnt) return;
    int nt = min(TT, cnt - base);

    int t = threadIdx.x, wid = t >> 5, l = t & 31;
    int wm = wid & 3, wn = wid >> 2;   // warp grid 4(M) x 2(N)

    if (t < TT) {
        if (t < nt) {
            s_tok[t]  = g_tok[e * MAXN + base + t];
            s_gate[t] = g_gate[e * MAXN + base + t];
        } else {
            s_tok[t]  = g_tok[e * MAXN + base];
            s_gate[t] = 0.f;
        }
    }
    __syncthreads();

    char* bufs = dynsm;
    char* Hs   = dynsm + HS_OFF;
    const float* W1e = W1 + (size_t)e * RR * DD;
    const float* W2e = W2 + (size_t)e * DD * RR;

    uint32_t a1_lo = (uint32_t)(((l & 7) + ((l >> 3) & 1) * 8) * S1B + (l >> 4) * 16);
    uint32_t b1_lo = (uint32_t)(((l & 7) + (l >> 4) * 8) * S1B + ((l >> 3) & 1) * 16);
    uint32_t a2_lo = (uint32_t)(((l & 7) + ((l >> 3) & 1) * 8) * S2B + (l >> 4) * 16);
    uint32_t b2_lo = (uint32_t)(((l & 7) + (l >> 4) * 8) * S2B + ((l >> 3) & 1) * 16);
    uint32_t bufs_a = smem_u32(bufs);

    // ================= fc1: 16 chunks of 64 k =================
    float acc[2][4][4];
#pragma unroll
    for (int i = 0; i < 2; i++)
#pragma unroll
        for (int j = 0; j < 4; j++)
#pragma unroll
            for (int k = 0; k < 4; k++) acc[i][j][k] = 0.f;

    float4 pa[4][2], pb[2][2];
    auto ldg1 = [&](int c) {
        // A: 128 rows x 64 cols = 1024 units of 8 floats; 4/thread
#pragma unroll
        for (int j = 0; j < 4; j++) {
            int idx = t + j * 256;
            int r = idx >> 3, c8 = idx & 7;
            int tok = s_tok[r] >> 1;
            const float4* src = (const float4*)(x + (size_t)tok * DD + c * 64 + c8 * 8);
            pa[j][0] = src[0]; pa[j][1] = src[1];
        }
        // B: 64 rows x 8 c8 = 512 units; 2/thread
#pragma unroll
        for (int j = 0; j < 2; j++) {
            int idx = t + j * 256;
            int r = idx >> 3, c8 = idx & 7;
            const float4* src = (const float4*)(W1e + (size_t)r * DD + c * 64 + c8 * 8);
            pb[j][0] = src[0]; pb[j][1] = src[1];
        }
    };
    auto sts1 = [&](int buf) {
        char* As = bufs + buf * B1SZ;
        char* Bs = As + B1_BOFF;
#pragma unroll
        for (int j = 0; j < 4; j++) {
            int idx = t + j * 256;
            int r = idx >> 3, c8 = idx & 7;
            *(uint4*)(As + r * S1B + c8 * 16) = pack8(pa[j][0], pa[j][1]);
        }
#pragma unroll
        for (int j = 0; j < 2; j++) {
            int idx = t + j * 256;
            int r = idx >> 3, c8 = idx & 7;
            *(uint4*)(Bs + r * S1B + c8 * 16) = pack8(pb[j][0], pb[j][1]);
        }
    };

    ldg1(0); sts1(0);
    __syncthreads();

    for (int c = 0; c < 16; c++) {
        int buf = c & 1;
        if (c + 1 < 16) ldg1(c + 1);
        uint32_t Aaddr = bufs_a + buf * B1SZ;
        uint32_t Baddr = Aaddr + B1_BOFF;
#pragma unroll
        for (int kk = 0; kk < 4; kk++) {
            uint32_t a[2][4], b[2][4];
#pragma unroll
            for (int mt = 0; mt < 2; mt++)
                ldsm4(a[mt], Aaddr + (wm * 32 + mt * 16) * S1B + kk * 32 + a1_lo);
#pragma unroll
            for (int pr = 0; pr < 2; pr++)
                ldsm4(b[pr], Baddr + (wn * 32 + pr * 16) * S1B + kk * 32 + b1_lo);
#pragma unroll
            for (int mt = 0; mt < 2; mt++)
#pragma unroll
                for (int ntl = 0; ntl < 4; ntl++)
                    mma16816(acc[mt][ntl], a[mt], &b[ntl >> 1][(ntl & 1) * 2]);
        }
        if (c + 1 < 16) sts1((c + 1) & 1);
        __syncthreads();
    }

    // ============ epilogue: gelu*gate*2 -> fp16 H in smem ============
#pragma unroll
    for (int mt = 0; mt < 2; mt++) {
#pragma unroll
        for (int ntl = 0; ntl < 4; ntl++) {
#pragma unroll
            for (int half = 0; half < 2; half++) {
                int r = wm * 32 + mt * 16 + half * 8 + (l >> 2);
                float gs = s_gate[r] * 2.0f;   // SCALING = 128/64
                float v0 = acc[mt][ntl][half * 2 + 0];
                float v1 = acc[mt][ntl][half * 2 + 1];
                float g0 = 0.5f * v0 * (1.f + erff(v0 * 0.70710678118654752f)) * gs;
                float g1 = 0.5f * v1 * (1.f + erff(v1 * 0.70710678118654752f)) * gs;
                int n = wn * 32 + ntl * 8 + (l & 3) * 2;
                *(uint32_t*)(Hs + r * S2B + n * 2) = h2(g0, g1);
            }
        }
    }
    __syncthreads();

    // ================= fc2: 8 chunks of 128 output cols (K=64) =============
    uint32_t HsA = smem_u32(Hs);
    float4 pw[4][2];
    auto ldg2 = [&](int nch) {
        // W chunk: 128 rows x 8 c8 = 1024 units; 4/thread
#pragma unroll
        for (int j = 0; j < 4; j++) {
            int idx = t + j * 256;
            int r = idx >> 3, c8 = idx & 7;
            const float4* src = (const float4*)(W2e + (size_t)(nch * TT + r) * RR + c8 * 8);
            pw[j][0] = src[0]; pw[j][1] = src[1];
        }
    };
    auto sts2 = [&](int buf) {
        char* Ws = bufs + buf * B2SZ;
#pragma unroll
        for (int j = 0; j < 4; j++) {
            int idx = t + j * 256;
            int r = idx >> 3, c8 = idx & 7;
            *(uint4*)(Ws + r * S2B + c8 * 16) = pack8(pw[j][0], pw[j][1]);
        }
    };

    ldg2(0); sts2(0);
    __syncthreads();

    for (int n = 0; n < 8; n++) {
        int buf = n & 1;
        if (n + 1 < 8) ldg2(n + 1);
        float acc2[2][8][4];
#pragma unroll
        for (int i = 0; i < 2; i++)
#pragma unroll
            for (int j = 0; j < 8; j++)
#pragma unroll
                for (int k = 0; k < 4; k++) acc2[i][j][k] = 0.f;

        uint32_t Waddr = bufs_a + buf * B2SZ;
#pragma unroll
        for (int kk = 0; kk < 4; kk++) {
            uint32_t a[2][4], b[4][4];
#pragma unroll
            for (int mt = 0; mt < 2; mt++)
                ldsm4(a[mt], HsA + (wm * 32 + mt * 16) * S2B + kk * 32 + a2_lo);
#pragma unroll
            for (int pr = 0; pr < 4; pr++)
                ldsm4(b[pr], Waddr + (wn * 64 + pr * 16) * S2B + kk * 32 + b2_lo);
#pragma unroll
            for (int mt = 0; mt < 2; mt++)
#pragma unroll
                for (int ntl = 0; ntl < 8; ntl++)
                    mma16816(acc2[mt][ntl], a[mt], &b[ntl >> 1][(ntl & 1) * 2]);
        }
        // store to scratch
#pragma unroll
        for (int mt = 0; mt < 2; mt++) {
#pragma unroll
            for (int half = 0; half < 2; half++) {
                int r = wm * 32 + mt * 16 + half * 8 + (l >> 2);
                if (r < nt) {
                    int slot = s_tok[r];
                    float* dst = g_scratch + (size_t)slot * DD + n * 128
                               + wn * 64 + (l & 3) * 2;
#pragma unroll
                    for (int ntl = 0; ntl < 8; ntl++)
                        *(float2*)(dst + ntl * 8) =
                            make_float2(acc2[mt][ntl][half * 2 + 0],
                                        acc2[mt][ntl][half * 2 + 1]);
                }
            }
        }
        if (n + 1 < 8) sts2((n + 1) & 1);
        __syncthreads();
    }
}

// ---------------------------------------------------------------------------
__global__ void combine_kernel(float* __restrict__ out, int N) {
    int i = blockIdx.x * blockDim.x + threadIdx.x;
    int total = N * (DD / 4);
    if (i >= total) return;
    int tok = i >> 8;
    int dd  = i & 255;
    const float4* s = (const float4*)g_scratch;
    float4 a = s[(size_t)tok * 512 + dd];
    float4 b = s[(size_t)tok * 512 + 256 + dd];
    float4 o;
    o.x = a.x + b.x; o.y = a.y + b.y; o.z = a.z + b.z; o.w = a.w + b.w;
    ((float4*)out)[i] = o;
}

// ---------------------------------------------------------------------------
extern "C" void kernel_launch(void* const* d_in, const int* in_sizes, int n_in,
                              void* d_out, int out_size) {
    const float* x  = (const float*)d_in[0];
    const float* Wg = (const float*)d_in[1];
    const float* bg = (const float*)d_in[2];
    const float* W1 = (const float*)d_in[3];
    const float* W2 = (const float*)d_in[4];
    float* out = (float*)d_out;
    int N = in_sizes[0] / DD;

    cudaFuncSetAttribute(expert_kernel,
                         cudaFuncAttributeMaxDynamicSharedMemorySize, SMEM_TOTAL);

    void* counts_ptr = nullptr;
    cudaGetSymbolAddress(&counts_ptr, g_counts);
    cudaMemsetAsync(counts_ptr, 0, NE * sizeof(int), 0);

    router_kernel<<<(N + 31) / 32, 256>>>(x, Wg, bg, N);

    dim3 egrid(NE, 128);
    expert_kernel<<<egrid, 256, SMEM_TOTAL>>>(x, W1, W2);

    int total = N * (DD / 4);
    combine_kernel<<<(total + 255) / 256, 256>>>(out, N);
}